// round 15
// baseline (speedup 1.0000x reference)
#include <cuda_runtime.h>
#include <cuda_bf16.h>
#include <cstdint>

// Problem constants (fixed by the dataset)
#define NB    2048
#define NC    9605
#define TPB   256
#define TOPK  10
#define NROW  4                        // rows per group (float4 alignment: 4*9605 % 4 == 0)
#define NGRP  (NB / NROW)              // 512 groups
#define NCTA  (2 * NGRP)               // 1024 CTAs, two per group
#define QPG   ((NROW * NC) / 4)        // 9605 quads per group (exact)
#define QH    4803                     // split point: h=0 -> [0,QH), h=1 -> [QH,QPG)

#define CLIP      0.05f
#define EPS_F     1e-8f
#define ALPHA1    2.0f
#define ALPHA_OTH 0.5f

// LUT: piecewise-linear, slope-intercept vs global bin coordinate t
#define NBINS   1024
#define XMIN    (-8.0f)
#define BSCALE  64.0f                  // bins per unit x ([-8,8] -> [0,1024))
#define TOFF    512.0f                 // -XMIN*BSCALE

// candidate collection (row 10th-max of N(0,1) is ~3.05 sigma; thresh 2.5 ->
// ~60 candidates/row, P(<10) ~1e-15, P(>128) ~1e-17; fallback guards both)
#define THRESH  2.5f
#define CAP     128
#define YFLAG   (1 << 16)              // packed y!=0 flag in candidate index
#define CMASK   0xFFFF

__device__ float        g_partials[NCTA];
__device__ float        g_gadj[NGRP];
__device__ int          g_cnt[NB];        // zero-init; arbiter resets
__device__ int          g_hasrow[NB];     // bits 0..2 = has1/2/3; arbiter resets
__device__ uint2        g_cand[NB * CAP]; // (value bits, col|yflag)
__device__ int          g_gdone[NGRP];    // pair arrival counter; arbiter resets
__device__ unsigned int g_done = 0;       // global arrival counter; folder resets

__device__ __forceinline__ bool beatsP(float v, int i, float V, int I) {
    // jax.lax.top_k order: larger value first; ties -> lower col first
    return (v > V) || (v == V && (i & CMASK) < (I & CMASK));
}

// exact base*w for a single element (LUT build, epilogue, fallback)
__device__ __forceinline__ float elem_term(float xv, float yv) {
    float e  = __expf(-xv);
    float p  = __fdividef(1.0f, 1.0f + e);          // sigmoid
    float xn = fminf(1.0f - p + CLIP, 1.0f);
    bool  pos = (yv != 0.0f);
    float arg  = pos ? p : xn;
    float onem = 1.0f - arg;
    float o2   = onem * onem;
    float w    = pos ? onem : (o2 * o2);             // gamma 1 vs 4
    return __logf(fmaxf(arg, EPS_F)) * w;
}

struct LutPack { float c, s; };   // term = fma(t, s, c), t = global bin coord

__global__ void __launch_bounds__(TPB, 5)
fused_kernel(const float* __restrict__ x, const float* __restrict__ y,
             const int* __restrict__ compost, int n_compost,
             const int* __restrict__ recycle, int n_recycle,
             const int* __restrict__ donate,  int n_donate,
             const int* __restrict__ wl_map,
             float* __restrict__ out)
{
    __shared__ LutPack s_lut[2 * NBINS];            // 16 KB (reused for final fold)
    __shared__ float   s_wsum[TPB / 32];
    __shared__ float   s_adj[NROW];
    __shared__ int     s_arbiter;
    __shared__ int     s_islast;

    const int tid  = threadIdx.x;
    const int lane = tid & 31;
    const int wid  = tid >> 5;
    const int cta  = blockIdx.x;
    const int grp  = cta >> 1;
    const int half = cta & 1;
    const int row0 = grp * NROW;
    const long long ebase = (long long)grp * (NROW * NC);

    // ---- whitelist-flag gathers (both halves do all rows; ORs idempotent;
    //      loads issued early, latency hidden by the LUT build below) ----
    #pragma unroll
    for (int r = 0; r < NROW; r++) {
        const float* __restrict__ yr = y + ebase + (long long)r * NC;
        for (int k = tid; k < n_compost; k += TPB)
            if (yr[compost[k]] != 0.0f) atomicOr(&g_hasrow[row0 + r], 1);
        for (int k = tid; k < n_recycle; k += TPB)
            if (yr[recycle[k]] != 0.0f) atomicOr(&g_hasrow[row0 + r], 2);
        for (int k = tid; k < n_donate;  k += TPB)
            if (yr[donate[k]]  != 0.0f) atomicOr(&g_hasrow[row0 + r], 4);
    }

    // ---- build both LUTs (MUFU-heavy; overlaps the gathers above) ----
    const float h = 1.0f / BSCALE;
    for (int e = tid; e < 2 * NBINS; e += TPB) {
        int   b  = e & (NBINS - 1);
        float yv = (e >= NBINS) ? 1.0f : 0.0f;
        float x0 = XMIN + (float)b * h;
        float v0 = elem_term(x0, yv);
        float v1 = elem_term(x0 + h, yv);
        float sl = v1 - v0;
        s_lut[e].c = v0 - sl * (float)b;
        s_lut[e].s = sl;
    }
    __syncthreads();

    // ---- main streaming pass over this CTA's half of the 4-row group ----
    const float4* __restrict__ x4 = (const float4*)(x + ebase);
    const float4* __restrict__ y4 = (const float4*)(y + ebase);
    const int qstart = half ? QH : 0;
    const int qend   = half ? QPG : QH;

    float sum = 0.0f;

    auto accum = [&](float xs, float ys) {
        const LutPack* tab = (ys != 0.0f) ? s_lut + NBINS : s_lut;
        float t = fmaf(xs, BSCALE, TOFF);
        t = fminf(fmaxf(t, 0.0f), (float)NBINS - 0.01f);
        int i = (int)t;
        LutPack e = tab[i];
        sum += fmaf(t, e.s, e.c);
    };
    auto cand = [&](float xs, float ys, int e) {
        if (xs > THRESH) {
            int r   = (e >= 2 * NC) ? ((e >= 3 * NC) ? 3 : 2)
                                    : ((e >= NC) ? 1 : 0);
            int col = e - r * NC;
            int row = row0 + r;
            int p = atomicAdd(&g_cnt[row], 1);
            if (p < CAP)
                g_cand[row * CAP + p] =
                    make_uint2(__float_as_uint(xs),
                               (unsigned)(col | ((ys != 0.0f) ? YFLAG : 0)));
        }
    };
    auto quad = [&](float4 xv, float4 yv, int q) {
        accum(xv.x, yv.x); accum(xv.y, yv.y);
        accum(xv.z, yv.z); accum(xv.w, yv.w);
        float m = fmaxf(fmaxf(xv.x, xv.y), fmaxf(xv.z, xv.w));
        if (m > THRESH) {
            int e = q << 2;
            cand(xv.x, yv.x, e + 0); cand(xv.y, yv.y, e + 1);
            cand(xv.z, yv.z, e + 2); cand(xv.w, yv.w, e + 3);
        }
    };

    int q = qstart + tid;
    for (; q + TPB < qend; q += 2 * TPB) {        // MLP_p1 = 4 (stay under Q_th)
        float4 xa = x4[q];        float4 ya = y4[q];
        float4 xb = x4[q + TPB];  float4 yb = y4[q + TPB];
        quad(xa, ya, q);
        quad(xb, yb, q + TPB);
    }
    for (; q < qend; q += TPB) {
        float4 xa = x4[q]; float4 ya = y4[q];
        quad(xa, ya, q);
    }

    // block sum reduce -> per-CTA partial
    #pragma unroll
    for (int off = 16; off >= 1; off >>= 1)
        sum += __shfl_down_sync(0xffffffffu, sum, off);
    if (lane == 0) s_wsum[wid] = sum;
    __syncthreads();

    if (tid == 0) {
        float t = 0.0f;
        #pragma unroll
        for (int w = 0; w < TPB / 32; w++) t += s_wsum[w];
        g_partials[cta] = t;
        __threadfence();
        int old = atomicAdd(&g_gdone[grp], 1);
        s_arbiter = (old == 1) ? 1 : 0;           // last of the pair
    }
    __syncthreads();

    // ---- group epilogue: last-arriving CTA of the pair (no waiting) ----
    if (s_arbiter) {
        __threadfence();                          // partner's candidates visible
        if (wid < NROW) {
            const int r   = wid;
            const int row = row0 + r;
            int cnt = g_cnt[row];
            bool fb = (cnt > CAP) || (cnt < TOPK);

            float tv[TOPK]; int ti[TOPK];
            if (!fb) {
                const uint2* __restrict__ bucket = g_cand + row * CAP;  // L2-hot
                float cv[CAP / 32]; int ci[CAP / 32];
                #pragma unroll
                for (int s = 0; s < CAP / 32; s++) {
                    int k = lane + 32 * s;
                    if (k < cnt) {
                        uint2 c = bucket[k];
                        cv[s] = __uint_as_float(c.x);
                        ci[s] = (int)c.y;
                    } else {
                        cv[s] = __int_as_float(0xff800000);
                        ci[s] = CMASK;
                    }
                }
                #pragma unroll
                for (int rr = 0; rr < TOPK; rr++) {
                    float bv = __int_as_float(0xff800000); int bi = CMASK; int bs = -1;
                    #pragma unroll
                    for (int s = 0; s < CAP / 32; s++)
                        if (beatsP(cv[s], ci[s], bv, bi)) { bv = cv[s]; bi = ci[s]; bs = s; }
                    float mv = bv; int mi = bi;
                    #pragma unroll
                    for (int off = 16; off >= 1; off >>= 1) {
                        float ov = __shfl_down_sync(0xffffffffu, mv, off);
                        int   oi = __shfl_down_sync(0xffffffffu, mi, off);
                        if (beatsP(ov, oi, mv, mi)) { mv = ov; mi = oi; }
                    }
                    mv = __shfl_sync(0xffffffffu, mv, 0);
                    mi = __shfl_sync(0xffffffffu, mi, 0);
                    if (bs >= 0 && bv == mv && bi == mi)   // unique col -> one owner
                        cv[bs] = __int_as_float(0xff800000);
                    tv[rr] = mv; ti[rr] = mi;
                }
            } else if (lane == 0) {
                // exact fallback (statistically never taken)
                const float* __restrict__ xr = x + ebase + (long long)r * NC;
                const float* __restrict__ yr = y + ebase + (long long)r * NC;
                #pragma unroll
                for (int t = 0; t < TOPK; t++) { tv[t] = __int_as_float(0xff800000); ti[t] = CMASK; }
                for (int j = 0; j < NC; j++) {
                    float v = xr[j];
                    if (beatsP(v, j, tv[TOPK-1], ti[TOPK-1])) {
                        tv[TOPK-1] = v; ti[TOPK-1] = j;
                        #pragma unroll
                        for (int k2 = TOPK - 1; k2 > 0; k2--) {
                            if (beatsP(tv[k2], ti[k2], tv[k2-1], ti[k2-1])) {
                                float fv = tv[k2]; tv[k2] = tv[k2-1]; tv[k2-1] = fv;
                                int   iv = ti[k2]; ti[k2] = ti[k2-1]; ti[k2-1] = iv;
                            }
                        }
                    }
                }
                #pragma unroll
                for (int t = 0; t < TOPK; t++)
                    if (yr[ti[t] & CMASK] != 0.0f) ti[t] |= YFLAG;
            }

            if (lane == 0) {
                int hb = g_hasrow[row];
                bool has1 = hb & 1, has2 = hb & 2, has3 = hb & 4;
                bool gt_only4 = !(has1 || has2 || has3);
                bool found = false;
                float mults[TOPK];
                #pragma unroll
                for (int k = 0; k < TOPK; k++) {
                    int wl = wl_map[ti[k] & CMASK];
                    bool in_map = wl > 0;
                    bool in_gt = ((wl == 1) && has1) || ((wl == 2) && has2) ||
                                 ((wl == 3) && has3) || ((wl == 4) && gt_only4);
                    float f = 1.0f;
                    if (in_map && gt_only4)          f *= ALPHA_OTH;
                    if (in_map && !in_gt && !found)  f *= ALPHA1;
                    mults[k] = f;
                    found = found || (in_map && in_gt);
                }
                float extra = found ? 1.0f : ALPHA1;
                float adj = 0.0f;
                #pragma unroll
                for (int k = 0; k < TOPK; k++) {
                    float m = mults[k] * extra;
                    if (m != 1.0f)
                        adj += elem_term(tv[k], (ti[k] & YFLAG) ? 1.0f : 0.0f) * (m - 1.0f);
                }
                s_adj[r] = adj;
                // reset per-row state for next graph replay (after reads)
                g_cnt[row]    = 0;
                g_hasrow[row] = 0;
            }
        }
        __syncthreads();
        if (tid == 0) {
            float a = 0.0f;
            #pragma unroll
            for (int r = 0; r < NROW; r++) a += s_adj[r];
            g_gadj[grp]   = a;
            g_gdone[grp]  = 0;          // reset pair counter for next replay
        }
    }

    // ---- global completion: last of all 1024 CTAs folds everything ----
    if (tid == 0) {
        __threadfence();
        unsigned int old = atomicAdd(&g_done, 1u);
        s_islast = (old == NCTA - 1) ? 1 : 0;
    }
    __syncthreads();

    if (s_islast) {
        __threadfence();
        float* s_red = (float*)s_lut;   // LUT no longer needed
        float s = 0.0f;
        for (int i = tid; i < NCTA; i += TPB) s += g_partials[i];
        for (int i = tid; i < NGRP; i += TPB) s += g_gadj[i];
        s_red[tid] = s;
        __syncthreads();
        for (int st = TPB / 2; st >= 1; st >>= 1) {
            if (tid < st) s_red[tid] += s_red[tid + st];
            __syncthreads();
        }
        if (tid == 0) {
            out[0] = -s_red[0];
            g_done = 0;                 // reset for next graph replay
        }
    }
}

extern "C" void kernel_launch(void* const* d_in, const int* in_sizes, int n_in,
                              void* d_out, int out_size)
{
    const float* x       = (const float*)d_in[0];
    const float* y       = (const float*)d_in[1];
    const int*   compost = (const int*)d_in[2];
    const int*   recycle = (const int*)d_in[3];
    const int*   donate  = (const int*)d_in[4];
    const int*   wl_map  = (const int*)d_in[5];

    fused_kernel<<<NCTA, TPB>>>(x, y,
                                compost, in_sizes[2],
                                recycle, in_sizes[3],
                                donate,  in_sizes[4],
                                wl_map,
                                (float*)d_out);
}

// round 16
// speedup vs baseline: 1.5682x; 1.5682x over previous
#include <cuda_runtime.h>
#include <cuda_bf16.h>
#include <cstdint>

// Problem constants (fixed by the dataset)
#define NB    2048
#define NC    9605
#define TPB   320                     // 10 warps; grid-limited occ 27.7 -> 34.6 warps/SM
#define NW    (TPB / 32)
#define TOPK  10
#define NROW  4                       // rows per CTA (float4 alignment: 4*9605 % 4 == 0)
#define NCTA  (NB / NROW)             // 512
#define QPC   ((NROW * NC) / 4)       // 9605 quads per CTA (exact)

#define CLIP      0.05f
#define EPS_F     1e-8f
#define ALPHA1    2.0f
#define ALPHA_OTH 0.5f

// LUT: piecewise-linear, slope-intercept vs global bin coordinate t
#define NBINS   1024
#define XMIN    (-8.0f)
#define BSCALE  64.0f                 // bins per unit x ([-8,8] -> [0,1024))
#define TOFF    512.0f                // -XMIN*BSCALE

// candidate collection (row 10th-max of N(0,1) is ~3.05 sigma; thresh 2.5 ->
// ~60 candidates/row, P(<10) ~1e-15, P(>128) ~1e-17; fallback guards both)
#define THRESH  2.5f
#define CAP     128
#define YFLAG   (1 << 16)             // packed y!=0 flag in candidate index
#define CMASK   0xFFFF

__device__ float        g_partials[NCTA];
__device__ unsigned int g_done = 0;

__device__ __forceinline__ bool beatsP(float v, int i, float V, int I) {
    // jax.lax.top_k order: larger value first; ties -> lower col first
    return (v > V) || (v == V && (i & CMASK) < (I & CMASK));
}

// exact base*w for a single element (LUT build, epilogue, fallback)
__device__ __forceinline__ float elem_term(float xv, float yv) {
    float e  = __expf(-xv);
    float p  = __fdividef(1.0f, 1.0f + e);          // sigmoid
    float xn = fminf(1.0f - p + CLIP, 1.0f);
    bool  pos = (yv != 0.0f);
    float arg  = pos ? p : xn;
    float onem = 1.0f - arg;
    float o2   = onem * onem;
    float w    = pos ? onem : (o2 * o2);             // gamma 1 vs 4
    return __logf(fmaxf(arg, EPS_F)) * w;
}

struct LutPack { float c, s; };   // term = fma(t, s, c), t = global bin coord

__global__ void __launch_bounds__(TPB, 4)
fused_kernel(const float* __restrict__ x, const float* __restrict__ y,
             const int* __restrict__ compost, int n_compost,
             const int* __restrict__ recycle, int n_recycle,
             const int* __restrict__ donate,  int n_donate,
             const int* __restrict__ wl_map,
             float* __restrict__ out)
{
    __shared__ LutPack s_lut[2 * NBINS];            // 16 KB (reused for final fold)
    __shared__ float   s_cv[NROW][CAP];
    __shared__ int     s_ci[NROW][CAP];
    __shared__ int     s_cnt[NROW];
    __shared__ int     s_has[NROW][3];
    __shared__ float   s_wsum[NW];
    __shared__ float   s_adj[NROW];
    __shared__ int     s_islast;

    const int tid  = threadIdx.x;
    const int lane = tid & 31;
    const int wid  = tid >> 5;
    const int cta  = blockIdx.x;
    const long long ebase = (long long)cta * (NROW * NC);

    // ---- init shared ----
    if (tid < NROW) { s_cnt[tid] = 0; s_adj[tid] = 0.0f; }
    if (tid < NROW * 3) ((int*)s_has)[tid] = 0;
    __syncthreads();   // s_has zero before gather stores

    // ---- whitelist-flag gathers (benign-race stores; latency overlaps LUT build) ----
    #pragma unroll
    for (int r = 0; r < NROW; r++) {
        const float* __restrict__ yr = y + ebase + (long long)r * NC;
        for (int k = tid; k < n_compost; k += TPB)
            if (yr[compost[k]] != 0.0f) s_has[r][0] = 1;
        for (int k = tid; k < n_recycle; k += TPB)
            if (yr[recycle[k]] != 0.0f) s_has[r][1] = 1;
        for (int k = tid; k < n_donate;  k += TPB)
            if (yr[donate[k]]  != 0.0f) s_has[r][2] = 1;
    }

    // ---- build both LUTs (MUFU-heavy; overlaps the gathers above) ----
    const float h = 1.0f / BSCALE;
    for (int e = tid; e < 2 * NBINS; e += TPB) {
        int   b  = e & (NBINS - 1);
        float yv = (e >= NBINS) ? 1.0f : 0.0f;
        float x0 = XMIN + (float)b * h;
        float v0 = elem_term(x0, yv);
        float v1 = elem_term(x0 + h, yv);
        float sl = v1 - v0;
        s_lut[e].c = v0 - sl * (float)b;
        s_lut[e].s = sl;
    }
    __syncthreads();

    // ---- main streaming pass over this CTA's 4 rows (unroll-2, MLP_p1=4) ----
    const float4* __restrict__ x4 = (const float4*)(x + ebase);
    const float4* __restrict__ y4 = (const float4*)(y + ebase);

    float sum = 0.0f;

    auto accum = [&](float xs, float ys) {
        const LutPack* tab = (ys != 0.0f) ? s_lut + NBINS : s_lut;
        float t = fmaf(xs, BSCALE, TOFF);
        t = fminf(fmaxf(t, 0.0f), (float)NBINS - 0.01f);
        int i = (int)t;
        LutPack e = tab[i];
        sum += fmaf(t, e.s, e.c);
    };
    auto cand = [&](float xs, float ys, int e) {
        if (xs > THRESH) {
            int r   = (e >= 2 * NC) ? ((e >= 3 * NC) ? 3 : 2)
                                    : ((e >= NC) ? 1 : 0);
            int col = e - r * NC;
            int p = atomicAdd(&s_cnt[r], 1);
            if (p < CAP) {
                s_cv[r][p] = xs;
                s_ci[r][p] = col | ((ys != 0.0f) ? YFLAG : 0);
            }
        }
    };
    auto quad = [&](float4 xv, float4 yv, int q) {
        accum(xv.x, yv.x); accum(xv.y, yv.y);
        accum(xv.z, yv.z); accum(xv.w, yv.w);
        float m = fmaxf(fmaxf(xv.x, xv.y), fmaxf(xv.z, xv.w));
        if (m > THRESH) {
            int e = q << 2;
            cand(xv.x, yv.x, e + 0); cand(xv.y, yv.y, e + 1);
            cand(xv.z, yv.z, e + 2); cand(xv.w, yv.w, e + 3);
        }
    };

    int q = tid;
    for (; q + TPB < QPC; q += 2 * TPB) {
        float4 xa = x4[q];        float4 ya = y4[q];
        float4 xb = x4[q + TPB];  float4 yb = y4[q + TPB];
        quad(xa, ya, q);
        quad(xb, yb, q + TPB);
    }
    for (; q < QPC; q += TPB) {
        float4 xa = x4[q]; float4 ya = y4[q];
        quad(xa, ya, q);
    }

    // block sum reduce
    #pragma unroll
    for (int off = 16; off >= 1; off >>= 1)
        sum += __shfl_down_sync(0xffffffffu, sum, off);
    if (lane == 0) s_wsum[wid] = sum;
    __syncthreads();   // candidates + flags + wsums all visible

    // ---- per-row top-10 + whitelist epilogue: warp r handles row r ----
    if (wid < NROW) {
        const int r = wid;
        int cnt = s_cnt[r];
        bool fb = (cnt > CAP) || (cnt < TOPK);

        float tv[TOPK]; int ti[TOPK];
        if (!fb) {
            float cv[CAP / 32]; int ci[CAP / 32];
            #pragma unroll
            for (int s = 0; s < CAP / 32; s++) {
                int k = lane + 32 * s;
                if (k < cnt) { cv[s] = s_cv[r][k]; ci[s] = s_ci[r][k]; }
                else         { cv[s] = __int_as_float(0xff800000); ci[s] = CMASK; }
            }
            #pragma unroll
            for (int rr = 0; rr < TOPK; rr++) {
                float bv = __int_as_float(0xff800000); int bi = CMASK; int bs = -1;
                #pragma unroll
                for (int s = 0; s < CAP / 32; s++)
                    if (beatsP(cv[s], ci[s], bv, bi)) { bv = cv[s]; bi = ci[s]; bs = s; }
                float mv = bv; int mi = bi;
                #pragma unroll
                for (int off = 16; off >= 1; off >>= 1) {
                    float ov = __shfl_down_sync(0xffffffffu, mv, off);
                    int   oi = __shfl_down_sync(0xffffffffu, mi, off);
                    if (beatsP(ov, oi, mv, mi)) { mv = ov; mi = oi; }
                }
                mv = __shfl_sync(0xffffffffu, mv, 0);
                mi = __shfl_sync(0xffffffffu, mi, 0);
                if (bs >= 0 && bv == mv && bi == mi)   // unique col -> one owner
                    cv[bs] = __int_as_float(0xff800000);
                tv[rr] = mv; ti[rr] = mi;
            }
        } else if (lane == 0) {
            // exact fallback (statistically never taken)
            const float* __restrict__ xr = x + ebase + (long long)r * NC;
            const float* __restrict__ yr = y + ebase + (long long)r * NC;
            #pragma unroll
            for (int t = 0; t < TOPK; t++) { tv[t] = __int_as_float(0xff800000); ti[t] = CMASK; }
            for (int j = 0; j < NC; j++) {
                float v = xr[j];
                if (beatsP(v, j, tv[TOPK-1], ti[TOPK-1])) {
                    tv[TOPK-1] = v; ti[TOPK-1] = j;
                    #pragma unroll
                    for (int k2 = TOPK - 1; k2 > 0; k2--) {
                        if (beatsP(tv[k2], ti[k2], tv[k2-1], ti[k2-1])) {
                            float fv = tv[k2]; tv[k2] = tv[k2-1]; tv[k2-1] = fv;
                            int   iv = ti[k2]; ti[k2] = ti[k2-1]; ti[k2-1] = iv;
                        }
                    }
                }
            }
            #pragma unroll
            for (int t = 0; t < TOPK; t++)
                if (yr[ti[t] & CMASK] != 0.0f) ti[t] |= YFLAG;
        }

        if (lane == 0) {
            bool has1 = s_has[r][0] != 0, has2 = s_has[r][1] != 0, has3 = s_has[r][2] != 0;
            bool gt_only4 = !(has1 || has2 || has3);
            bool found = false;
            float mults[TOPK];
            #pragma unroll
            for (int k = 0; k < TOPK; k++) {
                int wl = wl_map[ti[k] & CMASK];
                bool in_map = wl > 0;
                bool in_gt = ((wl == 1) && has1) || ((wl == 2) && has2) ||
                             ((wl == 3) && has3) || ((wl == 4) && gt_only4);
                float f = 1.0f;
                if (in_map && gt_only4)          f *= ALPHA_OTH;
                if (in_map && !in_gt && !found)  f *= ALPHA1;
                mults[k] = f;
                found = found || (in_map && in_gt);
            }
            float extra = found ? 1.0f : ALPHA1;
            float adj = 0.0f;
            #pragma unroll
            for (int k = 0; k < TOPK; k++) {
                float m = mults[k] * extra;
                if (m != 1.0f)
                    adj += elem_term(tv[k], (ti[k] & YFLAG) ? 1.0f : 0.0f) * (m - 1.0f);
            }
            s_adj[r] = adj;
        }
    }
    __syncthreads();

    if (tid == 0) {
        float t = 0.0f;
        #pragma unroll
        for (int w = 0; w < NW; w++) t += s_wsum[w];
        #pragma unroll
        for (int r = 0; r < NROW; r++) t += s_adj[r];
        g_partials[cta] = t;
        __threadfence();
        unsigned int old = atomicAdd(&g_done, 1u);
        s_islast = (old == NCTA - 1) ? 1 : 0;
    }
    __syncthreads();

    // ---- last CTA: fold all partials (deterministic fixed order) ----
    if (s_islast) {
        __threadfence();
        float* s_red = (float*)s_lut;   // LUT no longer needed
        float s = 0.0f;
        for (int i = tid; i < NCTA; i += TPB) s += g_partials[i];
        s_red[tid] = s;
        __syncthreads();
        // fold 320 -> 256, then binary tree
        if (tid < TPB - 256) s_red[tid] += s_red[tid + 256];
        __syncthreads();
        for (int st = 128; st >= 1; st >>= 1) {
            if (tid < st) s_red[tid] += s_red[tid + st];
            __syncthreads();
        }
        if (tid == 0) {
            out[0] = -s_red[0];
            g_done = 0;                 // reset for next graph replay
        }
    }
}

extern "C" void kernel_launch(void* const* d_in, const int* in_sizes, int n_in,
                              void* d_out, int out_size)
{
    const float* x       = (const float*)d_in[0];
    const float* y       = (const float*)d_in[1];
    const int*   compost = (const int*)d_in[2];
    const int*   recycle = (const int*)d_in[3];
    const int*   donate  = (const int*)d_in[4];
    const int*   wl_map  = (const int*)d_in[5];

    fused_kernel<<<NCTA, TPB>>>(x, y,
                                compost, in_sizes[2],
                                recycle, in_sizes[3],
                                donate,  in_sizes[4],
                                wl_map,
                                (float*)d_out);
}